// round 3
// baseline (speedup 1.0000x reference)
#include <cuda_runtime.h>
#include <math.h>

// Problem constants (from metadata / reference):
//   x:(8,4096,512) f32, router_w:(512,8), w1:(8,512,2048), b1:(8,2048),
//   w2:(8,2048,512), b2:(8,512). Output: out (8*4096*512) f32 + aux_loss (1).
#define NTOK 32768
#define DM   512
#define FF   2048
#define EE   8
#define NK   (NTOK * 2)
#define RBLK 512               // router blocks (64 tokens each)
#define RWARPS (RBLK * 8)      // 4096 warps, one partial row each

// ---------------- device scratch (static, no allocation) ----------------
__device__ float g_H[(size_t)NK * FF];      // 512 MB expert-hidden scratch
__device__ int   g_topk_idx[NK];
__device__ float g_topk_w[NK];
__device__ int   g_cnt[EE];
__device__ int   g_off[EE];
__device__ int   g_cur[EE];
__device__ int   g_top1[EE];
__device__ int   g_list[NK];                // token id per CSR slot
__device__ float g_wl[NK];                  // gate weight per CSR slot
__device__ float g_prob_part[RWARPS * EE];  // per-warp softmax-prob partial sums

// ---------------- zero small state ----------------
__global__ void zero_kernel() {
    int t = threadIdx.x;
    if (t < EE) { g_cnt[t] = 0; g_cur[t] = 0; g_top1[t] = 0; }
}

// ---------------- router: logits, top-2, gate weights, aux stats ----------------
__global__ __launch_bounds__(256) void router_kernel(
        const float* __restrict__ x, const float* __restrict__ rw) {
    __shared__ float s_rw[EE * DM];   // transposed router weights [e][d]
    int tid = threadIdx.x;
    for (int i = tid; i < DM * EE; i += 256) {
        int d = i >> 3, e = i & 7;
        s_rw[e * DM + d] = rw[i];
    }
    __syncthreads();

    int warp = tid >> 5, lane = tid & 31;
    float psum[EE];
#pragma unroll
    for (int e = 0; e < EE; e++) psum[e] = 0.f;

    for (int it = 0; it < 8; it++) {
        int t = blockIdx.x * 64 + warp * 8 + it;
        const float* xr = x + (size_t)t * DM;
        float acc[EE];
#pragma unroll
        for (int e = 0; e < EE; e++) acc[e] = 0.f;
#pragma unroll 4
        for (int j = 0; j < 16; j++) {
            float xv = xr[lane + 32 * j];
#pragma unroll
            for (int e = 0; e < EE; e++)
                acc[e] += xv * s_rw[e * DM + lane + 32 * j];
        }
#pragma unroll
        for (int e = 0; e < EE; e++) {
#pragma unroll
            for (int o = 16; o > 0; o >>= 1)
                acc[e] += __shfl_down_sync(0xffffffffu, acc[e], o);
        }
        if (lane == 0) {
            // top-2 (earliest index on ties, like jax top_k)
            int e0 = 0; float v0 = acc[0];
#pragma unroll
            for (int e = 1; e < EE; e++) if (acc[e] > v0) { v0 = acc[e]; e0 = e; }
            int e1 = -1; float v1 = -INFINITY;
#pragma unroll
            for (int e = 0; e < EE; e++)
                if (e != e0 && acc[e] > v1) { v1 = acc[e]; e1 = e; }
            float ex = expf(v1 - v0);
            float inv = 1.f / (1.f + ex);
            g_topk_idx[2 * t] = e0;  g_topk_idx[2 * t + 1] = e1;
            g_topk_w[2 * t] = inv;   g_topk_w[2 * t + 1] = ex * inv;
            atomicAdd(&g_cnt[e0], 1);
            atomicAdd(&g_cnt[e1], 1);
            atomicAdd(&g_top1[e0], 1);
            // full softmax for aux loss
            float s = 0.f; float pe[EE];
#pragma unroll
            for (int e = 0; e < EE; e++) { pe[e] = expf(acc[e] - v0); s += pe[e]; }
            float is = 1.f / s;
#pragma unroll
            for (int e = 0; e < EE; e++) psum[e] += pe[e] * is;
        }
    }
    if (lane == 0) {
        int wg = blockIdx.x * 8 + warp;
#pragma unroll
        for (int e = 0; e < EE; e++) g_prob_part[wg * EE + e] = psum[e];
    }
}

// ---------------- prep: CSR offsets + aux loss (deterministic fixed-order reduce) ----------------
__global__ void prep_kernel(float* __restrict__ out, int out_size) {
    __shared__ float s_part[256];
    __shared__ float s_e[EE];
    int t = threadIdx.x;
    int e = t & 7, chunk = t >> 3;       // 32 chunks of 128 warps
    float s = 0.f;
    int w0 = chunk * 128;
    for (int w = w0; w < w0 + 128; w++) s += g_prob_part[w * EE + e];
    s_part[t] = s;
    __syncthreads();
    if (t < EE) {
        float tot = 0.f;
        for (int c = 0; c < 32; c++) tot += s_part[c * 8 + t];
        s_e[t] = tot;
    }
    __syncthreads();
    if (t == 0) {
        int o = 0;
        for (int ee = 0; ee < EE; ee++) { g_off[ee] = o; o += g_cnt[ee]; }
        float aux = 0.f;
        const float invN = 1.f / (float)NTOK;
        for (int ee = 0; ee < EE; ee++)
            aux += (s_e[ee] * invN) * ((float)g_top1[ee] * invN);
        aux *= 0.01f * (float)EE;
        if (out_size > NTOK * DM) out[(size_t)NTOK * DM] = aux;
    }
}

// ---------------- scatter tokens into per-expert CSR slots ----------------
__global__ void scatter_kernel() {
    int t = blockIdx.x * 256 + threadIdx.x;
    if (t >= NTOK) return;
#pragma unroll
    for (int k = 0; k < 2; k++) {
        int e = g_topk_idx[2 * t + k];
        int p = atomicAdd(&g_cur[e], 1);
        int s = g_off[e] + p;
        g_list[s] = t;
        g_wl[s] = g_topk_w[2 * t + k];
    }
}

// ---------------- GEMM1: H = gelu(gather(x) @ w1[e] + b1[e]) ----------------
// tile 128x128, K-step 8, 256 threads, 8x8 per thread
__global__ __launch_bounds__(256, 2) void gemm1_kernel(
        const float* __restrict__ x,
        const float* __restrict__ w1,
        const float* __restrict__ b1) {
    int e = blockIdx.z;
    int cnt = g_cnt[e];
    int row0 = blockIdx.y * 128;
    if (row0 >= cnt) return;
    int off = g_off[e];
    int nb = blockIdx.x * 128;

    __shared__ float As[8][128];
    __shared__ float Bs[8][128];

    int t = threadIdx.x;
    // A load mapping: 2 threads per row, float4 each
    int ar = t >> 1;
    int ak = (t & 1) * 4;
    int grow_l = row0 + ar;
    int slot = off + min(grow_l, cnt - 1);
    int token = g_list[slot];
    const float4* xrow = (const float4*)(x + (size_t)token * DM);
    // B load mapping: 32 threads per k-row, float4 each
    int bk = t >> 5;
    int bn = (t & 31) * 4;
    const float* w1e = w1 + (size_t)e * DM * FF;

    int ty = t >> 4, tx = t & 15;
    float acc[8][8];
#pragma unroll
    for (int i = 0; i < 8; i++)
#pragma unroll
        for (int j = 0; j < 8; j++) acc[i][j] = 0.f;

    for (int kb = 0; kb < DM; kb += 8) {
        float4 av = xrow[(kb + ak) >> 2];
        As[ak + 0][ar] = av.x;
        As[ak + 1][ar] = av.y;
        As[ak + 2][ar] = av.z;
        As[ak + 3][ar] = av.w;
        float4 bv = *(const float4*)(w1e + (size_t)(kb + bk) * FF + nb + bn);
        *(float4*)&Bs[bk][bn] = bv;
        __syncthreads();
#pragma unroll
        for (int k = 0; k < 8; k++) {
            float a[8], b[8];
            *(float4*)&a[0] = *(const float4*)&As[k][ty * 8];
            *(float4*)&a[4] = *(const float4*)&As[k][ty * 8 + 4];
            *(float4*)&b[0] = *(const float4*)&Bs[k][tx * 8];
            *(float4*)&b[4] = *(const float4*)&Bs[k][tx * 8 + 4];
#pragma unroll
            for (int i = 0; i < 8; i++)
#pragma unroll
                for (int j = 0; j < 8; j++) acc[i][j] += a[i] * b[j];
        }
        __syncthreads();
    }

    const float* b1e = b1 + (size_t)e * FF + nb;
#pragma unroll
    for (int i = 0; i < 8; i++) {
        int gr = row0 + ty * 8 + i;
        if (gr < cnt) {
            float* hrow = &g_H[(size_t)(off + gr) * FF + nb];
#pragma unroll
            for (int j = 0; j < 8; j++) {
                int c = tx * 8 + j;
                float v = acc[i][j] + b1e[c];
                // exact GELU: 0.5*v*(1+erf(v/sqrt(2)))
                hrow[c] = 0.5f * v * (1.0f + erff(v * 0.70710678118654752f));
            }
        }
    }
}

// ---------------- GEMM2: out += gate * (H @ w2[e] + b2[e]) ----------------
__global__ __launch_bounds__(256, 2) void gemm2_kernel(
        const float* __restrict__ w2,
        const float* __restrict__ b2,
        float* __restrict__ out) {
    int e = blockIdx.z;
    int cnt = g_cnt[e];
    int row0 = blockIdx.y * 128;
    if (row0 >= cnt) return;
    int off = g_off[e];
    int nb = blockIdx.x * 128;

    __shared__ float As[8][128];
    __shared__ float Bs[8][128];

    int t = threadIdx.x;
    int ar = t >> 1;
    int ak = (t & 1) * 4;
    int grow_l = row0 + ar;
    const float4* hrow = (const float4*)(g_H + (size_t)(off + min(grow_l, cnt - 1)) * FF);
    int bk = t >> 5;
    int bn = (t & 31) * 4;
    const float* w2e = w2 + (size_t)e * FF * DM;

    int ty = t >> 4, tx = t & 15;
    float acc[8][8];
#pragma unroll
    for (int i = 0; i < 8; i++)
#pragma unroll
        for (int j = 0; j < 8; j++) acc[i][j] = 0.f;

    for (int kb = 0; kb < FF; kb += 8) {
        float4 av = hrow[(kb + ak) >> 2];
        As[ak + 0][ar] = av.x;
        As[ak + 1][ar] = av.y;
        As[ak + 2][ar] = av.z;
        As[ak + 3][ar] = av.w;
        float4 bv = *(const float4*)(w2e + (size_t)(kb + bk) * DM + nb + bn);
        *(float4*)&Bs[bk][bn] = bv;
        __syncthreads();
#pragma unroll
        for (int k = 0; k < 8; k++) {
            float a[8], b[8];
            *(float4*)&a[0] = *(const float4*)&As[k][ty * 8];
            *(float4*)&a[4] = *(const float4*)&As[k][ty * 8 + 4];
            *(float4*)&b[0] = *(const float4*)&Bs[k][tx * 8];
            *(float4*)&b[4] = *(const float4*)&Bs[k][tx * 8 + 4];
#pragma unroll
            for (int i = 0; i < 8; i++)
#pragma unroll
                for (int j = 0; j < 8; j++) acc[i][j] += a[i] * b[j];
        }
        __syncthreads();
    }

    const float* b2e = b2 + (size_t)e * DM + nb;
#pragma unroll
    for (int i = 0; i < 8; i++) {
        int gr = row0 + ty * 8 + i;
        if (gr < cnt) {
            int tok = g_list[off + gr];
            float gw = g_wl[off + gr];
            float* orow = out + (size_t)tok * DM + nb;
#pragma unroll
            for (int j = 0; j < 8; j++) {
                int c = tx * 8 + j;
                float y = acc[i][j] + b2e[c];
                atomicAdd(&orow[c], gw * y);   // exactly 2 contributions/elem -> deterministic
            }
        }
    }
}

// ---------------- launch ----------------
extern "C" void kernel_launch(void* const* d_in, const int* in_sizes, int n_in,
                              void* d_out, int out_size) {
    const float* x  = (const float*)d_in[0];
    const float* rw = (const float*)d_in[1];
    const float* w1 = (const float*)d_in[2];
    const float* b1 = (const float*)d_in[3];
    const float* w2 = (const float*)d_in[4];
    const float* b2 = (const float*)d_in[5];
    float* out = (float*)d_out;

    cudaMemsetAsync(out, 0, (size_t)NTOK * DM * sizeof(float), 0);
    zero_kernel<<<1, 32>>>();
    router_kernel<<<RBLK, 256>>>(x, rw);
    prep_kernel<<<1, 256>>>(out, out_size);
    scatter_kernel<<<NTOK / 256, 256>>>();
    gemm1_kernel<<<dim3(FF / 128, NTOK / 128, EE), 256>>>(x, w1, b1);
    gemm2_kernel<<<dim3(DM / 128, NTOK / 128, EE), 256>>>(w2, b2, out);
}

// round 6
// speedup vs baseline: 2.0588x; 2.0588x over previous
#include <cuda_runtime.h>
#include <math.h>
#include <stdint.h>

// Problem: x:(8,4096,512) f32, router_w:(512,8), w1:(8,512,2048), b1:(8,2048),
//          w2:(8,2048,512), b2:(8,512). Output: out (8*4096*512) f32 + aux_loss.
#define NTOK 32768
#define DM   512
#define FF   2048
#define EE   8
#define NK   (NTOK * 2)
#define MAX_TILES 520
#define NKP_MAX (MAX_TILES * 128)
#define RBLK 512
#define RWARPS (RBLK * 8)

// ---------------- device scratch (static, no allocation) ----------------
__device__ float g_H[(size_t)NKP_MAX * FF];       // expert-hidden scratch
__device__ int   g_topk_idx[NK];
__device__ float g_topk_w[NK];
__device__ int   g_cnt[EE];
__device__ int   g_off[EE];
__device__ int   g_cur[EE];
__device__ int   g_top1[EE];
__device__ int   g_list[NKP_MAX];
__device__ float g_wl[NKP_MAX];
__device__ float g_prob_part[RWARPS * EE];
__device__ int   g_tile_e[MAX_TILES];
__device__ int   g_tile_base[MAX_TILES];
__device__ int   g_tile_valid[MAX_TILES];
__device__ int   g_ntiles;

__device__ __forceinline__ uint32_t f2tf32(float f) {
    uint32_t r; asm("cvt.rna.tf32.f32 %0, %1;" : "=r"(r) : "f"(f)); return r;
}
__device__ __forceinline__ void mma_tf32(float* d, const uint32_t* a, const uint32_t* b) {
    asm volatile(
        "mma.sync.aligned.m16n8k8.row.col.f32.tf32.tf32.f32 "
        "{%0,%1,%2,%3}, {%4,%5,%6,%7}, {%8,%9}, {%0,%1,%2,%3};\n"
        : "+f"(d[0]), "+f"(d[1]), "+f"(d[2]), "+f"(d[3])
        : "r"(a[0]), "r"(a[1]), "r"(a[2]), "r"(a[3]), "r"(b[0]), "r"(b[1]));
}
__device__ __forceinline__ float gelu_exact(float v) {
    return 0.5f * v * (1.0f + erff(v * 0.70710678118654752f));
}

// ---------------- zero small state ----------------
__global__ void zero_kernel() {
    int t = threadIdx.x;
    if (t < EE) { g_cnt[t] = 0; g_cur[t] = 0; g_top1[t] = 0; }
}

// ---------------- router ----------------
__global__ __launch_bounds__(256) void router_kernel(
        const float* __restrict__ x, const float* __restrict__ rw) {
    __shared__ float s_rw[EE * DM];
    int tid = threadIdx.x;
    for (int i = tid; i < DM * EE; i += 256) {
        int d = i >> 3, e = i & 7;
        s_rw[e * DM + d] = rw[i];
    }
    __syncthreads();
    int warp = tid >> 5, lane = tid & 31;
    float psum[EE];
#pragma unroll
    for (int e = 0; e < EE; e++) psum[e] = 0.f;
    for (int it = 0; it < 8; it++) {
        int t = blockIdx.x * 64 + warp * 8 + it;
        const float* xr = x + (size_t)t * DM;
        float acc[EE];
#pragma unroll
        for (int e = 0; e < EE; e++) acc[e] = 0.f;
#pragma unroll 4
        for (int j = 0; j < 16; j++) {
            float xv = xr[lane + 32 * j];
#pragma unroll
            for (int e = 0; e < EE; e++) acc[e] += xv * s_rw[e * DM + lane + 32 * j];
        }
#pragma unroll
        for (int e = 0; e < EE; e++) {
#pragma unroll
            for (int o = 16; o > 0; o >>= 1)
                acc[e] += __shfl_down_sync(0xffffffffu, acc[e], o);
        }
        if (lane == 0) {
            int e0 = 0; float v0 = acc[0];
#pragma unroll
            for (int e = 1; e < EE; e++) if (acc[e] > v0) { v0 = acc[e]; e0 = e; }
            int e1 = -1; float v1 = -INFINITY;
#pragma unroll
            for (int e = 0; e < EE; e++)
                if (e != e0 && acc[e] > v1) { v1 = acc[e]; e1 = e; }
            float ex = expf(v1 - v0);
            float inv = 1.f / (1.f + ex);
            g_topk_idx[2 * t] = e0;  g_topk_idx[2 * t + 1] = e1;
            g_topk_w[2 * t] = inv;   g_topk_w[2 * t + 1] = ex * inv;
            atomicAdd(&g_cnt[e0], 1);
            atomicAdd(&g_cnt[e1], 1);
            atomicAdd(&g_top1[e0], 1);
            float s = 0.f; float pe[EE];
#pragma unroll
            for (int e = 0; e < EE; e++) { pe[e] = expf(acc[e] - v0); s += pe[e]; }
            float is = 1.f / s;
#pragma unroll
            for (int e = 0; e < EE; e++) psum[e] += pe[e] * is;
        }
    }
    if (lane == 0) {
        int wg = blockIdx.x * 8 + warp;
#pragma unroll
        for (int e = 0; e < EE; e++) g_prob_part[wg * EE + e] = psum[e];
    }
}

// ---------------- prep: aligned CSR offsets, tile table, aux loss ----------------
__global__ void prep_kernel(float* __restrict__ out, int out_size) {
    __shared__ float s_part[256];
    __shared__ float s_e[EE];
    int t = threadIdx.x;
    int e = t & 7, chunk = t >> 3;
    float s = 0.f;
    int w0 = chunk * 128;
    for (int w = w0; w < w0 + 128; w++) s += g_prob_part[w * EE + e];
    s_part[t] = s;
    __syncthreads();
    if (t < EE) {
        float tot = 0.f;
        for (int c = 0; c < 32; c++) tot += s_part[c * 8 + t];
        s_e[t] = tot;
    }
    __syncthreads();
    if (t == 0) {
        int o = 0, nt = 0;
        for (int ee = 0; ee < EE; ee++) {
            g_off[ee] = o;
            int cnt = g_cnt[ee];
            int ntl = (cnt + 127) >> 7;
            for (int i = 0; i < ntl; i++) {
                g_tile_e[nt] = ee;
                g_tile_base[nt] = o + i * 128;
                int v = cnt - i * 128;
                g_tile_valid[nt] = v > 128 ? 128 : v;
                nt++;
            }
            o += ntl * 128;
        }
        g_ntiles = nt;
        float aux = 0.f;
        const float invN = 1.f / (float)NTOK;
        for (int ee = 0; ee < EE; ee++)
            aux += (s_e[ee] * invN) * ((float)g_top1[ee] * invN);
        aux *= 0.01f * (float)EE;
        if (out_size > NTOK * DM) out[(size_t)NTOK * DM] = aux;
    }
}

// ---------------- scatter + pad ----------------
__global__ void scatter_kernel() {
    int t = blockIdx.x * 256 + threadIdx.x;
    if (t >= NTOK) return;
#pragma unroll
    for (int k = 0; k < 2; k++) {
        int e = g_topk_idx[2 * t + k];
        int p = atomicAdd(&g_cur[e], 1);
        int s = g_off[e] + p;
        g_list[s] = t;
        g_wl[s] = g_topk_w[2 * t + k];
    }
}
__global__ void pad_kernel() {
    int s = blockIdx.x * 256 + threadIdx.x;
    if (s >= NKP_MAX) return;
    int e = EE - 1;
    for (int i = 1; i < EE; i++) if (s < g_off[i]) { e = i - 1; break; }
    if (s >= g_off[e] + g_cnt[e]) { g_list[s] = 0; g_wl[s] = 0.f; }
}

// ---------------- tf32 warp-MMA grouped GEMM ----------------
// Tile 128x128, BK=16, 256 threads = 8 warps (2x4), each warp 64x32.
// SMEM [k][m]/[k][n], stride 136 floats: conflict-free STS and fragment LDS.
#define SSTR 136

template<int PHASE>
__global__ __launch_bounds__(256) void moe_mma(
        const float* __restrict__ x,
        const float* __restrict__ wmat,
        const float* __restrict__ bias_all,
        float* __restrict__ out) {
    constexpr int KD  = (PHASE == 1) ? DM : FF;   // reduction dim
    constexpr int ND  = (PHASE == 1) ? FF : DM;   // output dim (B row stride)
    constexpr int NIT = KD / 16;

    int tile = blockIdx.y;
    if (tile >= g_ntiles) return;
    int e     = g_tile_e[tile];
    int base  = g_tile_base[tile];
    int valid = g_tile_valid[tile];
    int nb    = blockIdx.x * 128;

    __shared__ float As[2][16][SSTR];
    __shared__ float Bs[2][16][SSTR];

    int t = threadIdx.x;
    int wid = t >> 5, lane = t & 31;
    int g  = lane >> 2;          // group id (0..7)
    int tg = lane & 3;           // thread-in-group (0..3)
    int warp_m = (wid >> 2) * 64;
    int warp_n = (wid & 3) * 32;

    // A loader mapping: row r = t&127, k-half kq = (t>>7)*8
    int r  = t & 127;
    int kq = (t >> 7) * 8;
    const float* arow;
    if (PHASE == 1) {
        int tok = g_list[base + r];
        arow = x + (size_t)tok * DM;
    } else {
        arow = g_H + (size_t)(base + r) * FF;
    }
    // B loader mapping: k-row kr = t>>4, col block (t&15)*8
    int kr  = t >> 4;
    int bn8 = (t & 15) * 8;
    const float* Bsrc = wmat + (size_t)e * KD * ND + nb;  // [k][n], row stride ND

    float acc[4][4][4];
#pragma unroll
    for (int mt = 0; mt < 4; mt++)
#pragma unroll
        for (int nt = 0; nt < 4; nt++)
#pragma unroll
            for (int i = 0; i < 4; i++) acc[mt][nt][i] = 0.f;

    // ---- prolog: stage 0 ----
    {
        float la[8], lb[8];
        *(float4*)&la[0] = *(const float4*)(arow + kq);
        *(float4*)&la[4] = *(const float4*)(arow + kq + 4);
        const float* bp = Bsrc + (size_t)kr * ND + bn8;
        *(float4*)&lb[0] = *(const float4*)(bp);
        *(float4*)&lb[4] = *(const float4*)(bp + 4);
#pragma unroll
        for (int j = 0; j < 8; j++)
            As[0][kq + j][r] = __uint_as_float(f2tf32(la[j]));
        uint4 u0 = make_uint4(f2tf32(lb[0]), f2tf32(lb[1]), f2tf32(lb[2]), f2tf32(lb[3]));
        uint4 u1 = make_uint4(f2tf32(lb[4]), f2tf32(lb[5]), f2tf32(lb[6]), f2tf32(lb[7]));
        *(uint4*)&Bs[0][kr][bn8]     = u0;
        *(uint4*)&Bs[0][kr][bn8 + 4] = u1;
        __syncthreads();
    }

    for (int it = 0; it < NIT; it++) {
        int s = it & 1;
        bool more = (it + 1 < NIT);
        float la[8], lb[8];
        if (more) {
            int kb = (it + 1) * 16;
            *(float4*)&la[0] = *(const float4*)(arow + kb + kq);
            *(float4*)&la[4] = *(const float4*)(arow + kb + kq + 4);
            const float* bp = Bsrc + (size_t)(kb + kr) * ND + bn8;
            *(float4*)&lb[0] = *(const float4*)(bp);
            *(float4*)&lb[4] = *(const float4*)(bp + 4);
        }
        // ---- compute 2 k8-steps from stage s ----
#pragma unroll
        for (int ks = 0; ks < 2; ks++) {
            int krow = ks * 8 + tg;
            uint32_t af[4][4], bf[4][2];
#pragma unroll
            for (int mt = 0; mt < 4; mt++) {
                int m0 = warp_m + mt * 16 + g;
                af[mt][0] = __float_as_uint(As[s][krow][m0]);
                af[mt][1] = __float_as_uint(As[s][krow][m0 + 8]);
                af[mt][2] = __float_as_uint(As[s][krow + 4][m0]);
                af[mt][3] = __float_as_uint(As[s][krow + 4][m0 + 8]);
            }
#pragma unroll
            for (int nt = 0; nt < 4; nt++) {
                int n0 = warp_n + nt * 8 + g;
                bf[nt][0] = __float_as_uint(Bs[s][krow][n0]);
                bf[nt][1] = __float_as_uint(Bs[s][krow + 4][n0]);
            }
#pragma unroll
            for (int mt = 0; mt < 4; mt++)
#pragma unroll
                for (int nt = 0; nt < 4; nt++)
                    mma_tf32(acc[mt][nt], af[mt], bf[nt]);
        }
        if (more) {
            int sn = s ^ 1;
#pragma unroll
            for (int j = 0; j < 8; j++)
                As[sn][kq + j][r] = __uint_as_float(f2tf32(la[j]));
            uint4 u0 = make_uint4(f2tf32(lb[0]), f2tf32(lb[1]), f2tf32(lb[2]), f2tf32(lb[3]));
            uint4 u1 = make_uint4(f2tf32(lb[4]), f2tf32(lb[5]), f2tf32(lb[6]), f2tf32(lb[7]));
            *(uint4*)&Bs[sn][kr][bn8]     = u0;
            *(uint4*)&Bs[sn][kr][bn8 + 4] = u1;
            __syncthreads();
        }
    }

    // ---------------- epilogue ----------------
    // Fragment D mapping: c0:(row=g, col=tg*2) c1:(col+1) c2:(row+8) c3:(row+8,col+1)
    const float* bvec = bias_all + (size_t)e * ND + nb;
    if (PHASE == 1) {
#pragma unroll
        for (int mt = 0; mt < 4; mt++) {
            int rr0 = warp_m + mt * 16 + g;
            float* H0 = g_H + (size_t)(base + rr0) * FF + nb;
            float* H1 = g_H + (size_t)(base + rr0 + 8) * FF + nb;
#pragma unroll
            for (int nt = 0; nt < 4; nt++) {
                int c = warp_n + nt * 8 + tg * 2;
                float b0 = bvec[c], b1 = bvec[c + 1];
                float2 v0, v1;
                v0.x = gelu_exact(acc[mt][nt][0] + b0);
                v0.y = gelu_exact(acc[mt][nt][1] + b1);
                v1.x = gelu_exact(acc[mt][nt][2] + b0);
                v1.y = gelu_exact(acc[mt][nt][3] + b1);
                *(float2*)(H0 + c) = v0;
                *(float2*)(H1 + c) = v1;
            }
        }
    } else {
#pragma unroll
        for (int mt = 0; mt < 4; mt++) {
            int rr0 = warp_m + mt * 16 + g;
#pragma unroll
            for (int half = 0; half < 2; half++) {
                int rr = rr0 + half * 8;
                if (rr < valid) {
                    int slot = base + rr;
                    int tok  = g_list[slot];
                    float gw = g_wl[slot];
                    float* O = out + (size_t)tok * DM + nb;
#pragma unroll
                    for (int nt = 0; nt < 4; nt++) {
                        int c = warp_n + nt * 8 + tg * 2;
                        atomicAdd(O + c,     gw * (acc[mt][nt][half * 2]     + bvec[c]));
                        atomicAdd(O + c + 1, gw * (acc[mt][nt][half * 2 + 1] + bvec[c + 1]));
                    }
                }
            }
        }
    }
}

// ---------------- launch ----------------
extern "C" void kernel_launch(void* const* d_in, const int* in_sizes, int n_in,
                              void* d_out, int out_size) {
    const float* x  = (const float*)d_in[0];
    const float* rw = (const float*)d_in[1];
    const float* w1 = (const float*)d_in[2];
    const float* b1 = (const float*)d_in[3];
    const float* w2 = (const float*)d_in[4];
    const float* b2 = (const float*)d_in[5];
    float* out = (float*)d_out;

    cudaMemsetAsync(out, 0, (size_t)NTOK * DM * sizeof(float), 0);
    zero_kernel<<<1, 32>>>();
    router_kernel<<<RBLK, 256>>>(x, rw);
    prep_kernel<<<1, 256>>>(out, out_size);
    scatter_kernel<<<NTOK / 256, 256>>>();
    pad_kernel<<<NKP_MAX / 256, 256>>>();
    moe_mma<1><<<dim3(FF / 128, MAX_TILES), 256>>>(x, w1, b1, nullptr);
    moe_mma<2><<<dim3(DM / 128, MAX_TILES), 256>>>(x, w2, b2, out);
}

// round 7
// speedup vs baseline: 2.7787x; 1.3497x over previous
#include <cuda_runtime.h>
#include <math.h>
#include <stdint.h>

// Problem: x:(8,4096,512) f32, router_w:(512,8), w1:(8,512,2048), b1:(8,2048),
//          w2:(8,2048,512), b2:(8,512). Output: out (8*4096*512) f32 + aux_loss.
#define NTOK 32768
#define DM   512
#define FF   2048
#define EE   8
#define NK   (NTOK * 2)
#define MAX_TILES 520
#define NKP_MAX (MAX_TILES * 128)
#define RBLK 512
#define RWARPS (RBLK * 8)

// ---------------- device scratch (static, no allocation) ----------------
__device__ float g_H[(size_t)NKP_MAX * FF];       // expert-hidden scratch
__device__ int   g_topk_idx[NK];
__device__ float g_topk_w[NK];
__device__ int   g_cnt[EE];
__device__ int   g_off[EE];
__device__ int   g_cur[EE];
__device__ int   g_top1[EE];
__device__ int   g_list[NKP_MAX];
__device__ float g_wl[NKP_MAX];
__device__ float g_prob_part[RWARPS * EE];
__device__ int   g_tile_e[MAX_TILES];
__device__ int   g_tile_base[MAX_TILES];
__device__ int   g_tile_valid[MAX_TILES];
__device__ int   g_ntiles;

__device__ __forceinline__ uint32_t f2tf32(float f) {
    uint32_t r; asm("cvt.rna.tf32.f32 %0, %1;" : "=r"(r) : "f"(f)); return r;
}
__device__ __forceinline__ void mma_tf32(float* d, const uint32_t* a, const uint32_t* b) {
    asm volatile(
        "mma.sync.aligned.m16n8k8.row.col.f32.tf32.tf32.f32 "
        "{%0,%1,%2,%3}, {%4,%5,%6,%7}, {%8,%9}, {%0,%1,%2,%3};\n"
        : "+f"(d[0]), "+f"(d[1]), "+f"(d[2]), "+f"(d[3])
        : "r"(a[0]), "r"(a[1]), "r"(a[2]), "r"(a[3]), "r"(b[0]), "r"(b[1]));
}
__device__ __forceinline__ float gelu_exact(float v) {
    return 0.5f * v * (1.0f + erff(v * 0.70710678118654752f));
}

// ---------------- zero small state ----------------
__global__ void zero_kernel() {
    int t = threadIdx.x;
    if (t < EE) { g_cnt[t] = 0; g_cur[t] = 0; g_top1[t] = 0; }
}

// ---------------- router ----------------
__global__ __launch_bounds__(256) void router_kernel(
        const float* __restrict__ x, const float* __restrict__ rw) {
    __shared__ float s_rw[EE * DM];
    int tid = threadIdx.x;
    for (int i = tid; i < DM * EE; i += 256) {
        int d = i >> 3, e = i & 7;
        s_rw[e * DM + d] = rw[i];
    }
    __syncthreads();
    int warp = tid >> 5, lane = tid & 31;
    float psum[EE];
#pragma unroll
    for (int e = 0; e < EE; e++) psum[e] = 0.f;
    for (int it = 0; it < 8; it++) {
        int t = blockIdx.x * 64 + warp * 8 + it;
        const float* xr = x + (size_t)t * DM;
        float acc[EE];
#pragma unroll
        for (int e = 0; e < EE; e++) acc[e] = 0.f;
#pragma unroll 4
        for (int j = 0; j < 16; j++) {
            float xv = xr[lane + 32 * j];
#pragma unroll
            for (int e = 0; e < EE; e++) acc[e] += xv * s_rw[e * DM + lane + 32 * j];
        }
#pragma unroll
        for (int e = 0; e < EE; e++) {
#pragma unroll
            for (int o = 16; o > 0; o >>= 1)
                acc[e] += __shfl_down_sync(0xffffffffu, acc[e], o);
        }
        if (lane == 0) {
            int e0 = 0; float v0 = acc[0];
#pragma unroll
            for (int e = 1; e < EE; e++) if (acc[e] > v0) { v0 = acc[e]; e0 = e; }
            int e1 = -1; float v1 = -INFINITY;
#pragma unroll
            for (int e = 0; e < EE; e++)
                if (e != e0 && acc[e] > v1) { v1 = acc[e]; e1 = e; }
            float ex = expf(v1 - v0);
            float inv = 1.f / (1.f + ex);
            g_topk_idx[2 * t] = e0;  g_topk_idx[2 * t + 1] = e1;
            g_topk_w[2 * t] = inv;   g_topk_w[2 * t + 1] = ex * inv;
            atomicAdd(&g_cnt[e0], 1);
            atomicAdd(&g_cnt[e1], 1);
            atomicAdd(&g_top1[e0], 1);
            float s = 0.f; float pe[EE];
#pragma unroll
            for (int e = 0; e < EE; e++) { pe[e] = expf(acc[e] - v0); s += pe[e]; }
            float is = 1.f / s;
#pragma unroll
            for (int e = 0; e < EE; e++) psum[e] += pe[e] * is;
        }
    }
    if (lane == 0) {
        int wg = blockIdx.x * 8 + warp;
#pragma unroll
        for (int e = 0; e < EE; e++) g_prob_part[wg * EE + e] = psum[e];
    }
}

// ---------------- prep: aligned CSR offsets, tile table, aux loss ----------------
__global__ void prep_kernel(float* __restrict__ out, int out_size) {
    __shared__ float s_part[256];
    __shared__ float s_e[EE];
    int t = threadIdx.x;
    int e = t & 7, chunk = t >> 3;
    float s = 0.f;
    int w0 = chunk * 128;
    for (int w = w0; w < w0 + 128; w++) s += g_prob_part[w * EE + e];
    s_part[t] = s;
    __syncthreads();
    if (t < EE) {
        float tot = 0.f;
        for (int c = 0; c < 32; c++) tot += s_part[c * 8 + t];
        s_e[t] = tot;
    }
    __syncthreads();
    if (t == 0) {
        int o = 0, nt = 0;
        for (int ee = 0; ee < EE; ee++) {
            g_off[ee] = o;
            int cnt = g_cnt[ee];
            int ntl = (cnt + 127) >> 7;
            for (int i = 0; i < ntl; i++) {
                g_tile_e[nt] = ee;
                g_tile_base[nt] = o + i * 128;
                int v = cnt - i * 128;
                g_tile_valid[nt] = v > 128 ? 128 : v;
                nt++;
            }
            o += ntl * 128;
        }
        g_ntiles = nt;
        float aux = 0.f;
        const float invN = 1.f / (float)NTOK;
        for (int ee = 0; ee < EE; ee++)
            aux += (s_e[ee] * invN) * ((float)g_top1[ee] * invN);
        aux *= 0.01f * (float)EE;
        if (out_size > NTOK * DM) out[(size_t)NTOK * DM] = aux;
    }
}

// ---------------- scatter + pad ----------------
__global__ void scatter_kernel() {
    int t = blockIdx.x * 256 + threadIdx.x;
    if (t >= NTOK) return;
#pragma unroll
    for (int k = 0; k < 2; k++) {
        int e = g_topk_idx[2 * t + k];
        int p = atomicAdd(&g_cur[e], 1);
        int s = g_off[e] + p;
        g_list[s] = t;
        g_wl[s] = g_topk_w[2 * t + k];
    }
}
__global__ void pad_kernel() {
    int s = blockIdx.x * 256 + threadIdx.x;
    if (s >= NKP_MAX) return;
    int e = EE - 1;
    for (int i = 1; i < EE; i++) if (s < g_off[i]) { e = i - 1; break; }
    if (s >= g_off[e] + g_cnt[e]) { g_list[s] = 0; g_wl[s] = 0.f; }
}

// ---------------- tf32 warp-MMA grouped GEMM ----------------
// CTA tile 128x256, BK=16, 256 threads = 8 warps (2x4), warp tile 64x64.
// Dynamic SMEM: A [2][16][136], B [2][16][264] (strides keep LDS conflict-free).
#define ASTR 136
#define BSTR 264
#define A_ST (16 * ASTR)            // floats per A stage
#define B_ST (16 * BSTR)            // floats per B stage
#define SMEM_FLOATS (2 * A_ST + 2 * B_ST)
#define SMEM_BYTES  (SMEM_FLOATS * 4)

template<int PHASE>
__global__ __launch_bounds__(256, 1) void moe_mma(
        const float* __restrict__ x,
        const float* __restrict__ wmat,
        const float* __restrict__ bias_all,
        float* __restrict__ out) {
    constexpr int KD  = (PHASE == 1) ? DM : FF;   // reduction dim
    constexpr int ND  = (PHASE == 1) ? FF : DM;   // output dim (B row stride)
    constexpr int NIT = KD / 16;

    int tile = blockIdx.y;
    if (tile >= g_ntiles) return;
    int e     = g_tile_e[tile];
    int base  = g_tile_base[tile];
    int valid = g_tile_valid[tile];
    int nb    = blockIdx.x * 256;

    extern __shared__ float sm[];
    // As[s][k][m] = sm[s*A_ST + k*ASTR + m]
    // Bs[s][k][n] = sm[2*A_ST + s*B_ST + k*BSTR + n]
    float* Abase = sm;
    float* Bbase = sm + 2 * A_ST;

    int t = threadIdx.x;
    int wid = t >> 5, lane = t & 31;
    int g  = lane >> 2;          // 0..7
    int tg = lane & 3;           // 0..3
    int warp_m = (wid >> 2) * 64;
    int warp_n = (wid & 3) * 64;

    // A loader: row r = t&127, k-half kq = (t>>7)*8
    int r  = t & 127;
    int kq = (t >> 7) * 8;
    const float* arow;
    if (PHASE == 1) {
        int tok = g_list[base + r];
        arow = x + (size_t)tok * DM;
    } else {
        arow = g_H + (size_t)(base + r) * FF;
    }
    // B loader: k-row kr = t>>4, col block bn8 = (t&15)*8, two halves (+0, +128)
    int kr  = t >> 4;
    int bn8 = (t & 15) * 8;
    const float* Bsrc = wmat + (size_t)e * KD * ND + nb;  // [k][n], row stride ND

    float acc[4][8][4];
#pragma unroll
    for (int mt = 0; mt < 4; mt++)
#pragma unroll
        for (int nt = 0; nt < 8; nt++)
#pragma unroll
            for (int i = 0; i < 4; i++) acc[mt][nt][i] = 0.f;

    // ---- prolog: stage 0 ----
    {
        float la[8], lb0[8], lb1[8];
        *(float4*)&la[0] = *(const float4*)(arow + kq);
        *(float4*)&la[4] = *(const float4*)(arow + kq + 4);
        const float* bp = Bsrc + (size_t)kr * ND + bn8;
        *(float4*)&lb0[0] = *(const float4*)(bp);
        *(float4*)&lb0[4] = *(const float4*)(bp + 4);
        *(float4*)&lb1[0] = *(const float4*)(bp + 128);
        *(float4*)&lb1[4] = *(const float4*)(bp + 132);
        float* As0 = Abase;
#pragma unroll
        for (int j = 0; j < 8; j++)
            As0[(kq + j) * ASTR + r] = __uint_as_float(f2tf32(la[j]));
        float* Brow = Bbase + kr * BSTR + bn8;
        *(uint4*)(Brow)       = make_uint4(f2tf32(lb0[0]), f2tf32(lb0[1]), f2tf32(lb0[2]), f2tf32(lb0[3]));
        *(uint4*)(Brow + 4)   = make_uint4(f2tf32(lb0[4]), f2tf32(lb0[5]), f2tf32(lb0[6]), f2tf32(lb0[7]));
        *(uint4*)(Brow + 128) = make_uint4(f2tf32(lb1[0]), f2tf32(lb1[1]), f2tf32(lb1[2]), f2tf32(lb1[3]));
        *(uint4*)(Brow + 132) = make_uint4(f2tf32(lb1[4]), f2tf32(lb1[5]), f2tf32(lb1[6]), f2tf32(lb1[7]));
        __syncthreads();
    }

    for (int it = 0; it < NIT; it++) {
        int s = it & 1;
        bool more = (it + 1 < NIT);
        float la[8], lb0[8], lb1[8];
        if (more) {
            int kb = (it + 1) * 16;
            *(float4*)&la[0] = *(const float4*)(arow + kb + kq);
            *(float4*)&la[4] = *(const float4*)(arow + kb + kq + 4);
            const float* bp = Bsrc + (size_t)(kb + kr) * ND + bn8;
            *(float4*)&lb0[0] = *(const float4*)(bp);
            *(float4*)&lb0[4] = *(const float4*)(bp + 4);
            *(float4*)&lb1[0] = *(const float4*)(bp + 128);
            *(float4*)&lb1[4] = *(const float4*)(bp + 132);
        }
        const float* As = Abase + s * A_ST;
        const float* Bs = Bbase + s * B_ST;
        // ---- compute 2 k8-steps from stage s ----
#pragma unroll
        for (int ks = 0; ks < 2; ks++) {
            int krow = ks * 8 + tg;
            uint32_t af[4][4], bf[8][2];
#pragma unroll
            for (int mt = 0; mt < 4; mt++) {
                int m0 = warp_m + mt * 16 + g;
                af[mt][0] = __float_as_uint(As[krow * ASTR + m0]);
                af[mt][1] = __float_as_uint(As[krow * ASTR + m0 + 8]);
                af[mt][2] = __float_as_uint(As[(krow + 4) * ASTR + m0]);
                af[mt][3] = __float_as_uint(As[(krow + 4) * ASTR + m0 + 8]);
            }
#pragma unroll
            for (int nt = 0; nt < 8; nt++) {
                int n0 = warp_n + nt * 8 + g;
                bf[nt][0] = __float_as_uint(Bs[krow * BSTR + n0]);
                bf[nt][1] = __float_as_uint(Bs[(krow + 4) * BSTR + n0]);
            }
#pragma unroll
            for (int mt = 0; mt < 4; mt++)
#pragma unroll
                for (int nt = 0; nt < 8; nt++)
                    mma_tf32(acc[mt][nt], af[mt], bf[nt]);
        }
        if (more) {
            int sn = s ^ 1;
            float* Asn = Abase + sn * A_ST;
#pragma unroll
            for (int j = 0; j < 8; j++)
                Asn[(kq + j) * ASTR + r] = __uint_as_float(f2tf32(la[j]));
            float* Brow = Bbase + sn * B_ST + kr * BSTR + bn8;
            *(uint4*)(Brow)       = make_uint4(f2tf32(lb0[0]), f2tf32(lb0[1]), f2tf32(lb0[2]), f2tf32(lb0[3]));
            *(uint4*)(Brow + 4)   = make_uint4(f2tf32(lb0[4]), f2tf32(lb0[5]), f2tf32(lb0[6]), f2tf32(lb0[7]));
            *(uint4*)(Brow + 128) = make_uint4(f2tf32(lb1[0]), f2tf32(lb1[1]), f2tf32(lb1[2]), f2tf32(lb1[3]));
            *(uint4*)(Brow + 132) = make_uint4(f2tf32(lb1[4]), f2tf32(lb1[5]), f2tf32(lb1[6]), f2tf32(lb1[7]));
            __syncthreads();
        }
    }

    // ---------------- epilogue ----------------
    // Fragment D mapping: c0:(row=g, col=tg*2) c1:(col+1) c2:(row+8) c3:(row+8,col+1)
    const float* bvec = bias_all + (size_t)e * ND + nb;
    if (PHASE == 1) {
#pragma unroll
        for (int mt = 0; mt < 4; mt++) {
            int rr0 = warp_m + mt * 16 + g;
            float* H0 = g_H + (size_t)(base + rr0) * FF + nb;
            float* H1 = g_H + (size_t)(base + rr0 + 8) * FF + nb;
#pragma unroll
            for (int nt = 0; nt < 8; nt++) {
                int c = warp_n + nt * 8 + tg * 2;
                float b0 = bvec[c], b1 = bvec[c + 1];
                float2 v0, v1;
                v0.x = gelu_exact(acc[mt][nt][0] + b0);
                v0.y = gelu_exact(acc[mt][nt][1] + b1);
                v1.x = gelu_exact(acc[mt][nt][2] + b0);
                v1.y = gelu_exact(acc[mt][nt][3] + b1);
                *(float2*)(H0 + c) = v0;
                *(float2*)(H1 + c) = v1;
            }
        }
    } else {
#pragma unroll
        for (int mt = 0; mt < 4; mt++) {
            int rr0 = warp_m + mt * 16 + g;
#pragma unroll
            for (int half = 0; half < 2; half++) {
                int rr = rr0 + half * 8;
                if (rr < valid) {
                    int slot = base + rr;
                    int tok  = g_list[slot];
                    float gw = g_wl[slot];
                    float* O = out + (size_t)tok * DM + nb;
#pragma unroll
                    for (int nt = 0; nt < 8; nt++) {
                        int c = warp_n + nt * 8 + tg * 2;
                        atomicAdd(O + c,     gw * (acc[mt][nt][half * 2]     + bvec[c]));
                        atomicAdd(O + c + 1, gw * (acc[mt][nt][half * 2 + 1] + bvec[c + 1]));
                    }
                }
            }
        }
    }
}

// ---------------- launch ----------------
extern "C" void kernel_launch(void* const* d_in, const int* in_sizes, int n_in,
                              void* d_out, int out_size) {
    const float* x  = (const float*)d_in[0];
    const float* rw = (const float*)d_in[1];
    const float* w1 = (const float*)d_in[2];
    const float* b1 = (const float*)d_in[3];
    const float* w2 = (const float*)d_in[4];
    const float* b2 = (const float*)d_in[5];
    float* out = (float*)d_out;

    cudaFuncSetAttribute(moe_mma<1>, cudaFuncAttributeMaxDynamicSharedMemorySize, SMEM_BYTES);
    cudaFuncSetAttribute(moe_mma<2>, cudaFuncAttributeMaxDynamicSharedMemorySize, SMEM_BYTES);

    cudaMemsetAsync(out, 0, (size_t)NTOK * DM * sizeof(float), 0);
    zero_kernel<<<1, 32>>>();
    router_kernel<<<RBLK, 256>>>(x, rw);
    prep_kernel<<<1, 256>>>(out, out_size);
    scatter_kernel<<<NTOK / 256, 256>>>();
    pad_kernel<<<NKP_MAX / 256, 256>>>();
    moe_mma<1><<<dim3(FF / 256, MAX_TILES), 256, SMEM_BYTES>>>(x, w1, b1, nullptr);
    moe_mma<2><<<dim3(DM / 256, MAX_TILES), 256, SMEM_BYTES>>>(x, w2, b2, out);
}